// round 2
// baseline (speedup 1.0000x reference)
#include <cuda_runtime.h>

// Local_Layer: GAT-style attention over M=32 neighbors, H=8 heads, D=16.
// score[n,m,h] = relu( dot(q[n,h],Wq[h]) + dot(k[n,m,h],Wk[h]) + b[h] )
// attn = softmax over m; out[n,h,:] = sum_m attn * k[n,m,h,:]
// Pure HBM-streaming problem: s[] is 819 MB, read exactly once, coalesced.

constexpr int M = 32, H = 8, D = 16, HID = 128;

__global__ __launch_bounds__(256, 8) void gat_local_kernel(
    const float* __restrict__ hq,   // [N, 128]
    const float* __restrict__ s,    // [N, 32, 128]
    const float* __restrict__ W,    // [8, 32]  (first 16 = q part, last 16 = k part)
    const float* __restrict__ b,    // [8]
    float* __restrict__ out,        // [N, 128]
    int n_nodes)
{
    __shared__ float sWq[HID];     // W[h][0:16] laid out as [h*16 + d]
    __shared__ float sWk[D * H];   // W[h][16+d] transposed -> [d*8 + h]
    __shared__ float qb[H];        // q-dot + bias per head
    __shared__ float sc[H * 33];   // scores, stride-33 padded (conflict-free)
    __shared__ float att[H * 33];  // attention weights, same layout
    __shared__ float obuf[8 * HID];// per-warp partial outputs

    const int n    = blockIdx.x;
    const int t    = threadIdx.x;       // 256 threads
    const int lane = t & 31;
    const int w    = t >> 5;
    const int m    = t >> 3;            // neighbor index 0..31
    const int hh   = t & 7;             // head index 0..7

    // --- Phase 0: each thread loads its contiguous 16-float k row (m, hh) ---
    const float4* sp = reinterpret_cast<const float4*>(s)
                     + ((size_t)n * (M * HID) + (size_t)t * 16) / 4;
    float4 a0 = sp[0], a1 = sp[1], a2 = sp[2], a3 = sp[3];
    float kk[16] = {a0.x, a0.y, a0.z, a0.w, a1.x, a1.y, a1.z, a1.w,
                    a2.x, a2.y, a2.z, a2.w, a3.x, a3.y, a3.z, a3.w};

    // Stage W into smem (q part row-major, k part transposed [d][h])
    if (t < 128) {
        sWq[t] = W[(t >> 4) * 32 + (t & 15)];
        sWk[(t >> 3) * 8 + (t & 7)] = W[(t & 7) * 32 + 16 + (t >> 3)];
    }
    __syncthreads();

    // --- Phase 1: q-dot per head (independent of m) ---
    if (t < 128) {
        float p = hq[(size_t)n * HID + t] * sWq[t];   // coalesced 512B read
        p += __shfl_xor_sync(0xffffffffu, p, 8);
        p += __shfl_xor_sync(0xffffffffu, p, 4);
        p += __shfl_xor_sync(0xffffffffu, p, 2);
        p += __shfl_xor_sync(0xffffffffu, p, 1);
        if ((t & 15) == 0) {
            int head = t >> 4;
            qb[head] = p + b[head];
        }
    }
    __syncthreads();

    // --- Phase 2: k-dot score, all in registers; sWk reads are conflict-free ---
    float acc = qb[hh];
    #pragma unroll
    for (int d = 0; d < D; d++) acc += kk[d] * sWk[d * 8 + hh];
    sc[hh * 33 + m] = fmaxf(acc, 0.0f);
    __syncthreads();

    // --- Phase 3: softmax over m, one warp per head (lane = m) ---
    {
        float v  = sc[w * 33 + lane];
        float mx = v;
        #pragma unroll
        for (int o = 16; o; o >>= 1)
            mx = fmaxf(mx, __shfl_xor_sync(0xffffffffu, mx, o));
        float e  = __expf(v - mx);
        float sm = e;
        #pragma unroll
        for (int o = 16; o; o >>= 1)
            sm += __shfl_xor_sync(0xffffffffu, sm, o);
        att[w * 33 + lane] = e / sm;
    }
    __syncthreads();

    // --- Phase 4: weighted sum over m without re-reading s ---
    float a = att[hh * 33 + m];
    float v[16];
    #pragma unroll
    for (int d = 0; d < 16; d++) v[d] = a * kk[d];
    // lanes {l, l^8, l^16, l^24} share the same head; collapse them
    #pragma unroll
    for (int d = 0; d < 16; d++) v[d] += __shfl_xor_sync(0xffffffffu, v[d], 8);
    #pragma unroll
    for (int d = 0; d < 16; d++) v[d] += __shfl_xor_sync(0xffffffffu, v[d], 16);
    if (lane < 8) {            // lane == head; holds sum over m in {4w..4w+3}
        #pragma unroll
        for (int d = 0; d < 16; d++)
            obuf[w * HID + lane * 16 + d] = v[d];
    }
    __syncthreads();

    // --- Phase 5: combine 8 warp partials, coalesced 512B store ---
    if (t < 128) {
        float o = 0.0f;
        #pragma unroll
        for (int ww = 0; ww < 8; ww++) o += obuf[ww * HID + t];
        out[(size_t)n * HID + t] = o;
    }
}

extern "C" void kernel_launch(void* const* d_in, const int* in_sizes, int n_in,
                              void* d_out, int out_size) {
    const float* h = (const float*)d_in[0];
    const float* s = (const float*)d_in[1];
    const float* W = (const float*)d_in[2];
    const float* b = (const float*)d_in[3];
    float* out     = (float*)d_out;
    int n_nodes = in_sizes[0] / HID;
    gat_local_kernel<<<n_nodes, 256>>>(h, s, W, b, out, n_nodes);
}

// round 3
// speedup vs baseline: 1.8300x; 1.8300x over previous
#include <cuda_runtime.h>

// Local_Layer: GAT-style attention over M=32 neighbors, H=8 heads, D=16.
// score[n,m,h] = relu( qdot[h] + dot(k[n,m,h],Wk[h]) + b[h] )
// attn = softmax over m; out[n,h,:] = sum_m attn * k[n,m,h,:]
//
// R3: fully-coalesced loads. Thread t owns float4 tile indices {t, t+256, t+512,
// t+768} of the node's 16KB s-tile -> each warp request is 512B contiguous
// (minimum 4 L1 wavefronts, vs 16 in R2). Decode: float4 #(j*256+t) is row
// (m = j*8 + warp, h = lane>>2, quarter = lane&3).

constexpr int M = 32, H = 8, D = 16, HID = 128;

__global__ __launch_bounds__(256, 8) void gat_local_kernel(
    const float* __restrict__ hq,   // [N, 128]
    const float* __restrict__ s,    // [N, 32, 128]
    const float* __restrict__ W,    // [8, 32]  (cols 0:16 = q part, 16:32 = k part)
    const float* __restrict__ b,    // [8]
    float* __restrict__ out,        // [N, 128]
    int n_nodes)
{
    __shared__ float sWq[HID];        // W[h][0:16] as [h*16 + d]
    __shared__ float sWk[H * D];      // W[h][16+d] as [h*16 + d] (float4-readable)
    __shared__ float qb[H];           // q-dot + bias per head
    __shared__ float sc[H * 33];      // scores, stride-33 padded
    __shared__ float att[H * 33];     // attention weights
    __shared__ float obuf[8 * HID];   // per-warp partial outputs

    const int n    = blockIdx.x;
    const int t    = threadIdx.x;     // 256 threads
    const int lane = t & 31;
    const int w    = t >> 5;          // warp id 0..7
    const int hh   = lane >> 2;       // head owned by this lane group
    const int d4   = lane & 3;        // quarter of the 16-float row
    (void)d4;

    // --- Phase 0: coalesced tile load. r[j] = row (m=j*8+w, h=hh, quarter=d4) ---
    const float4* sp = reinterpret_cast<const float4*>(s) + (size_t)n * (M * HID / 4);
    float4 r0 = sp[t];
    float4 r1 = sp[256 + t];
    float4 r2 = sp[512 + t];
    float4 r3 = sp[768 + t];

    // Stage W into smem
    if (t < 128) {
        sWq[t] = W[(t >> 4) * 32 + (t & 15)];
        sWk[t] = W[(t >> 4) * 32 + 16 + (t & 15)];
    }
    __syncthreads();

    // --- Phase 1: q-dot per head (independent of m) ---
    if (t < 128) {
        float p = hq[(size_t)n * HID + t] * sWq[t];   // coalesced 512B read
        p += __shfl_xor_sync(0xffffffffu, p, 8);
        p += __shfl_xor_sync(0xffffffffu, p, 4);
        p += __shfl_xor_sync(0xffffffffu, p, 2);
        p += __shfl_xor_sync(0xffffffffu, p, 1);
        if ((t & 15) == 0) {
            int head = t >> 4;
            qb[head] = p + b[head];
        }
    }
    __syncthreads();

    // --- Phase 2: k-dot scores. Each 4-lane group reduces one (m,h) row ---
    {
        const float4 wk = reinterpret_cast<const float4*>(sWk)[lane]; // Wk[hh][4*d4..+3]
        const float qbh = qb[hh];
        float4 rr[4] = {r0, r1, r2, r3};
        #pragma unroll
        for (int j = 0; j < 4; j++) {
            float p = rr[j].x * wk.x + rr[j].y * wk.y + rr[j].z * wk.z + rr[j].w * wk.w;
            p += __shfl_xor_sync(0xffffffffu, p, 1);
            p += __shfl_xor_sync(0xffffffffu, p, 2);
            if ((lane & 3) == 0)
                sc[hh * 33 + j * 8 + w] = fmaxf(p + qbh, 0.0f);
        }
    }
    __syncthreads();

    // --- Phase 3: softmax over m, one warp per head (lane = m) ---
    {
        float v  = sc[w * 33 + lane];
        float mx = v;
        #pragma unroll
        for (int o = 16; o; o >>= 1)
            mx = fmaxf(mx, __shfl_xor_sync(0xffffffffu, mx, o));
        float e  = __expf(v - mx);
        float sm = e;
        #pragma unroll
        for (int o = 16; o; o >>= 1)
            sm += __shfl_xor_sync(0xffffffffu, sm, o);
        att[w * 33 + lane] = e / sm;
    }
    __syncthreads();

    // --- Phase 4: weighted sum. Thread accumulates its 4 floats over its 4 m's ---
    {
        float4 acc = {0.f, 0.f, 0.f, 0.f};
        float a;
        a = att[hh * 33 + 0 * 8 + w];
        acc.x += a * r0.x; acc.y += a * r0.y; acc.z += a * r0.z; acc.w += a * r0.w;
        a = att[hh * 33 + 1 * 8 + w];
        acc.x += a * r1.x; acc.y += a * r1.y; acc.z += a * r1.z; acc.w += a * r1.w;
        a = att[hh * 33 + 2 * 8 + w];
        acc.x += a * r2.x; acc.y += a * r2.y; acc.z += a * r2.z; acc.w += a * r2.w;
        a = att[hh * 33 + 3 * 8 + w];
        acc.x += a * r3.x; acc.y += a * r3.y; acc.z += a * r3.z; acc.w += a * r3.w;
        // lane's output slot is out[lane*4 .. +3]; stage per-warp partials
        reinterpret_cast<float4*>(obuf)[w * 32 + lane] = acc;
    }
    __syncthreads();

    // --- Phase 5: combine 8 warp partials, coalesced 512B store ---
    if (t < 128) {
        float o = 0.0f;
        #pragma unroll
        for (int ww = 0; ww < 8; ww++) o += obuf[ww * HID + t];
        out[(size_t)n * HID + t] = o;
    }
}

extern "C" void kernel_launch(void* const* d_in, const int* in_sizes, int n_in,
                              void* d_out, int out_size) {
    const float* h = (const float*)d_in[0];
    const float* s = (const float*)d_in[1];
    const float* W = (const float*)d_in[2];
    const float* b = (const float*)d_in[3];
    float* out     = (float*)d_out;
    int n_nodes = in_sizes[0] / HID;
    gat_local_kernel<<<n_nodes, 256>>>(h, s, W, b, out, n_nodes);
}

// round 4
// speedup vs baseline: 1.8543x; 1.0133x over previous
#include <cuda_runtime.h>

// Local_Layer: GAT-style attention over M=32 neighbors, H=8 heads, D=16.
// score[n,m,h] = relu( qdot[h] + dot(k[n,m,h],Wk[h]) + b[h] )
// attn = softmax over m; out[n,h,:] = sum_m attn * k[n,m,h,:]
//
// R3: fully-coalesced loads. Thread t owns float4 tile indices {t, t+256, t+512,
// t+768} of the node's 16KB s-tile -> each warp request is 512B contiguous
// (minimum 4 L1 wavefronts, vs 16 in R2). Decode: float4 #(j*256+t) is row
// (m = j*8 + warp, h = lane>>2, quarter = lane&3).

constexpr int M = 32, H = 8, D = 16, HID = 128;

__global__ __launch_bounds__(256, 8) void gat_local_kernel(
    const float* __restrict__ hq,   // [N, 128]
    const float* __restrict__ s,    // [N, 32, 128]
    const float* __restrict__ W,    // [8, 32]  (cols 0:16 = q part, 16:32 = k part)
    const float* __restrict__ b,    // [8]
    float* __restrict__ out,        // [N, 128]
    int n_nodes)
{
    __shared__ float sWq[HID];        // W[h][0:16] as [h*16 + d]
    __shared__ float sWk[H * D];      // W[h][16+d] as [h*16 + d] (float4-readable)
    __shared__ float qb[H];           // q-dot + bias per head
    __shared__ float sc[H * 33];      // scores, stride-33 padded
    __shared__ float att[H * 33];     // attention weights
    __shared__ float obuf[8 * HID];   // per-warp partial outputs

    const int n    = blockIdx.x;
    const int t    = threadIdx.x;     // 256 threads
    const int lane = t & 31;
    const int w    = t >> 5;          // warp id 0..7
    const int hh   = lane >> 2;       // head owned by this lane group
    const int d4   = lane & 3;        // quarter of the 16-float row
    (void)d4;

    // --- Phase 0: coalesced tile load. r[j] = row (m=j*8+w, h=hh, quarter=d4) ---
    const float4* sp = reinterpret_cast<const float4*>(s) + (size_t)n * (M * HID / 4);
    float4 r0 = sp[t];
    float4 r1 = sp[256 + t];
    float4 r2 = sp[512 + t];
    float4 r3 = sp[768 + t];

    // Stage W into smem
    if (t < 128) {
        sWq[t] = W[(t >> 4) * 32 + (t & 15)];
        sWk[t] = W[(t >> 4) * 32 + 16 + (t & 15)];
    }
    __syncthreads();

    // --- Phase 1: q-dot per head (independent of m) ---
    if (t < 128) {
        float p = hq[(size_t)n * HID + t] * sWq[t];   // coalesced 512B read
        p += __shfl_xor_sync(0xffffffffu, p, 8);
        p += __shfl_xor_sync(0xffffffffu, p, 4);
        p += __shfl_xor_sync(0xffffffffu, p, 2);
        p += __shfl_xor_sync(0xffffffffu, p, 1);
        if ((t & 15) == 0) {
            int head = t >> 4;
            qb[head] = p + b[head];
        }
    }
    __syncthreads();

    // --- Phase 2: k-dot scores. Each 4-lane group reduces one (m,h) row ---
    {
        const float4 wk = reinterpret_cast<const float4*>(sWk)[lane]; // Wk[hh][4*d4..+3]
        const float qbh = qb[hh];
        float4 rr[4] = {r0, r1, r2, r3};
        #pragma unroll
        for (int j = 0; j < 4; j++) {
            float p = rr[j].x * wk.x + rr[j].y * wk.y + rr[j].z * wk.z + rr[j].w * wk.w;
            p += __shfl_xor_sync(0xffffffffu, p, 1);
            p += __shfl_xor_sync(0xffffffffu, p, 2);
            if ((lane & 3) == 0)
                sc[hh * 33 + j * 8 + w] = fmaxf(p + qbh, 0.0f);
        }
    }
    __syncthreads();

    // --- Phase 3: softmax over m, one warp per head (lane = m) ---
    {
        float v  = sc[w * 33 + lane];
        float mx = v;
        #pragma unroll
        for (int o = 16; o; o >>= 1)
            mx = fmaxf(mx, __shfl_xor_sync(0xffffffffu, mx, o));
        float e  = __expf(v - mx);
        float sm = e;
        #pragma unroll
        for (int o = 16; o; o >>= 1)
            sm += __shfl_xor_sync(0xffffffffu, sm, o);
        att[w * 33 + lane] = e / sm;
    }
    __syncthreads();

    // --- Phase 4: weighted sum. Thread accumulates its 4 floats over its 4 m's ---
    {
        float4 acc = {0.f, 0.f, 0.f, 0.f};
        float a;
        a = att[hh * 33 + 0 * 8 + w];
        acc.x += a * r0.x; acc.y += a * r0.y; acc.z += a * r0.z; acc.w += a * r0.w;
        a = att[hh * 33 + 1 * 8 + w];
        acc.x += a * r1.x; acc.y += a * r1.y; acc.z += a * r1.z; acc.w += a * r1.w;
        a = att[hh * 33 + 2 * 8 + w];
        acc.x += a * r2.x; acc.y += a * r2.y; acc.z += a * r2.z; acc.w += a * r2.w;
        a = att[hh * 33 + 3 * 8 + w];
        acc.x += a * r3.x; acc.y += a * r3.y; acc.z += a * r3.z; acc.w += a * r3.w;
        // lane's output slot is out[lane*4 .. +3]; stage per-warp partials
        reinterpret_cast<float4*>(obuf)[w * 32 + lane] = acc;
    }
    __syncthreads();

    // --- Phase 5: combine 8 warp partials, coalesced 512B store ---
    if (t < 128) {
        float o = 0.0f;
        #pragma unroll
        for (int ww = 0; ww < 8; ww++) o += obuf[ww * HID + t];
        out[(size_t)n * HID + t] = o;
    }
}

extern "C" void kernel_launch(void* const* d_in, const int* in_sizes, int n_in,
                              void* d_out, int out_size) {
    const float* h = (const float*)d_in[0];
    const float* s = (const float*)d_in[1];
    const float* W = (const float*)d_in[2];
    const float* b = (const float*)d_in[3];
    float* out     = (float*)d_out;
    int n_nodes = in_sizes[0] / HID;
    gat_local_kernel<<<n_nodes, 256>>>(h, s, W, b, out, n_nodes);
}